// round 14
// baseline (speedup 1.0000x reference)
#include <cuda_runtime.h>
#include <cuda_pipeline.h>
#include <cuda_fp16.h>
#include <math.h>
#include <stdint.h>

#define B_   4
#define LQ_  2048
#define LK_  2048
#define XS_  1024
#define PD_  128
#define NSPLIT 4

// Device-global scratch (no allocation allowed).
__device__ __half g_wth[3 * PD_ * XS_];     // [mat][n][k] = half(W^T)
__device__ __half g_qh[B_ * LQ_ * PD_];     // projected q (half)
__device__ __half g_kh[B_ * LK_ * PD_];     // projected k (half)
__device__ __half g_vt[B_ * PD_ * LK_];     // projected v, TRANSPOSED [b][d][j]
__device__ float  g_po[NSPLIT * B_ * LQ_ * PD_];
__device__ float  g_ml[NSPLIT * B_ * LQ_ * 2];

// D += A*B, m16n8k16 f16 inputs, f32 accum. a: 4 words (8 halves), b: 2 words.
__device__ __forceinline__ void mma_f16(float* c, const uint32_t* a, const uint32_t* b) {
    asm volatile(
        "mma.sync.aligned.m16n8k16.row.col.f32.f16.f16.f32 "
        "{%0,%1,%2,%3}, {%4,%5,%6,%7}, {%8,%9}, {%0,%1,%2,%3};\n"
        : "+f"(c[0]), "+f"(c[1]), "+f"(c[2]), "+f"(c[3])
        : "r"(a[0]), "r"(a[1]), "r"(a[2]), "r"(a[3]), "r"(b[0]), "r"(b[1]));
}

__device__ __forceinline__ uint32_t h2u(__half2 h) {
    return *reinterpret_cast<uint32_t*>(&h);
}

// ---------------------------------------------------------------------------
// wcvt_kernel: one-time W fp32 -> half, transposed to [mat][n][k].
// ---------------------------------------------------------------------------
__global__ __launch_bounds__(256) void wcvt_kernel(
    const float* __restrict__ Wq, const float* __restrict__ Wk,
    const float* __restrict__ Wv)
{
    const int i = blockIdx.x * 256 + threadIdx.x;    // 0..98303
    const int mat = i / (PD_ * XS_ / 4);
    const int r = i % (PD_ * XS_ / 4);
    const int n = r >> 8;              // 0..127
    const int k4 = (r & 255) * 4;      // 0..1020
    const float* W = (mat == 0) ? Wq : ((mat == 1) ? Wk : Wv);
    const float f0 = W[(size_t)(k4 + 0) * PD_ + n];
    const float f1 = W[(size_t)(k4 + 1) * PD_ + n];
    const float f2 = W[(size_t)(k4 + 2) * PD_ + n];
    const float f3 = W[(size_t)(k4 + 3) * PD_ + n];
    __half2* dst = (__half2*)(g_wth + ((size_t)mat * PD_ + n) * XS_ + k4);
    dst[0] = __floats2half2_rn(f0, f1);
    dst[1] = __floats2half2_rn(f2, f3);
}

// ---------------------------------------------------------------------------
// Projection GEMM (fp16 m16n8k16), fused fp32->fp16 of A:
//   C[8192,128] = A[8192,1024]@W[1024,128]+b
// CTA tile 64x128, grid (128,3) = 384 CTAs.  __launch_bounds__(128,3) caps
// regs at 128 so 3 CTAs/SM are resident -> 444 slots: ONE wave, 3-deep
// latency hiding.  Structure identical to the R13 version (single-buffered
// fused-cvt A, double-buffered cp.async B).
// ---------------------------------------------------------------------------
#define PAW 20
#define PBW 20

__global__ __launch_bounds__(128, 3) void proj_kernel(
    const float* __restrict__ x, const float* __restrict__ y,
    const float* __restrict__ bq, const float* __restrict__ bk,
    const float* __restrict__ bv)
{
    __shared__ uint32_t As[64 * PAW];        // [m][k-words], single buffer
    __shared__ uint32_t Bs[2 * 128 * PBW];   // [buf][n][k-words]

    const int mat = blockIdx.y;
    const float* A = (mat == 0) ? x : y;
    const float* bias = (mat == 0) ? bq : ((mat == 1) ? bk : bv);
    const __half* Bw = g_wth + (size_t)mat * PD_ * XS_;
    const int row0 = blockIdx.x * 64;

    const int tid  = threadIdx.x;
    const int wid  = tid >> 5;
    const int lane = tid & 31;
    const int lr = lane >> 2, lc = lane & 3;
    const int rw = (wid & 1) * 32;
    const int cw = (wid >> 1) * 64;

    // prologue: stage A(0) to regs, launch B(0)
    float4 rA[4];
    #pragma unroll
    for (int i = 0; i < 2; i++) {
        const int g = tid + i * 128;
        const int m = g >> 2, c4 = g & 3;
        rA[2 * i]     = *(const float4*)(A + (size_t)(row0 + m) * XS_ + c4 * 8);
        rA[2 * i + 1] = *(const float4*)(A + (size_t)(row0 + m) * XS_ + c4 * 8 + 4);
    }
    #pragma unroll
    for (int i = 0; i < 4; i++) {
        const int g = tid + i * 128;
        const int n = g >> 2, cq = g & 3;
        __pipeline_memcpy_async(&Bs[n * PBW + cq * 4],
                                Bw + (size_t)n * XS_ + cq * 8, 16);
    }
    __pipeline_commit();

    float acc[2][8][4];
    #pragma unroll
    for (int mf = 0; mf < 2; mf++)
        #pragma unroll
        for (int nf = 0; nf < 8; nf++)
            #pragma unroll
            for (int r = 0; r < 4; r++) acc[mf][nf][r] = 0.0f;

    for (int c = 0; c < 32; c++) {
        const int buf = c & 1;
        __pipeline_wait_prior(0);   // B(c) landed
        __syncthreads();            // all warps done reading As(c-1)

        // Store A(c): pack fp32 regs -> half2 words -> one STS.128 per slot
        #pragma unroll
        for (int i = 0; i < 2; i++) {
            const int g = tid + i * 128;
            const int m = g >> 2, c4 = g & 3;
            uint4 w;
            w.x = h2u(__floats2half2_rn(rA[2*i].x,   rA[2*i].y));
            w.y = h2u(__floats2half2_rn(rA[2*i].z,   rA[2*i].w));
            w.z = h2u(__floats2half2_rn(rA[2*i+1].x, rA[2*i+1].y));
            w.w = h2u(__floats2half2_rn(rA[2*i+1].z, rA[2*i+1].w));
            *(uint4*)&As[m * PAW + c4 * 4] = w;
        }
        __syncthreads();            // As(c) visible

        if (c < 31) {
            const int kc = (c + 1) * 32;
            #pragma unroll
            for (int i = 0; i < 2; i++) {
                const int g = tid + i * 128;
                const int m = g >> 2, c4 = g & 3;
                rA[2 * i]     = *(const float4*)(A + (size_t)(row0 + m) * XS_ + kc + c4 * 8);
                rA[2 * i + 1] = *(const float4*)(A + (size_t)(row0 + m) * XS_ + kc + c4 * 8 + 4);
            }
            const int nb = (c + 1) & 1;
            #pragma unroll
            for (int i = 0; i < 4; i++) {
                const int g = tid + i * 128;
                const int n = g >> 2, cq = g & 3;
                __pipeline_memcpy_async(&Bs[nb * 128 * PBW + n * PBW + cq * 4],
                                        Bw + (size_t)n * XS_ + kc + cq * 8, 16);
            }
            __pipeline_commit();
        }

        const uint32_t* Bb = Bs + buf * 128 * PBW;
        #pragma unroll
        for (int kf = 0; kf < 2; kf++) {
            const int kw = kf * 8;
            uint32_t a[2][4];
            #pragma unroll
            for (int mf = 0; mf < 2; mf++) {
                const int r = rw + mf * 16 + lr;
                a[mf][0] = As[r * PAW + kw + lc];
                a[mf][1] = As[(r + 8) * PAW + kw + lc];
                a[mf][2] = As[r * PAW + kw + lc + 4];
                a[mf][3] = As[(r + 8) * PAW + kw + lc + 4];
            }
            #pragma unroll
            for (int nf = 0; nf < 8; nf++) {
                uint32_t b[2];
                const int col = cw + nf * 8 + lr;
                b[0] = Bb[col * PBW + kw + lc];
                b[1] = Bb[col * PBW + kw + lc + 4];
                mma_f16(acc[0][nf], a[0], b);
                mma_f16(acc[1][nf], a[1], b);
            }
        }
    }

    // Epilogue: +bias, round to half.  Q/K natural layout; V transposed [b][d][j].
    #pragma unroll
    for (int mf = 0; mf < 2; mf++) {
        #pragma unroll
        for (int nf = 0; nf < 8; nf++) {
            const int row = row0 + rw + mf * 16 + lr;
            const int col = cw + nf * 8 + 2 * lc;
            const float2 bb = *(const float2*)(bias + col);
            const float v00 = acc[mf][nf][0] + bb.x;
            const float v01 = acc[mf][nf][1] + bb.y;
            const float v10 = acc[mf][nf][2] + bb.x;
            const float v11 = acc[mf][nf][3] + bb.y;
            if (mat < 2) {
                __half* C = (mat == 0) ? g_qh : g_kh;
                *(__half2*)(C + (size_t)row * PD_ + col) = __floats2half2_rn(v00, v01);
                *(__half2*)(C + (size_t)(row + 8) * PD_ + col) = __floats2half2_rn(v10, v11);
            } else {
                const int bi = row >> 11, j = row & 2047;   // row+8 stays same b
                g_vt[((size_t)bi * PD_ + col) * LK_ + j]         = __float2half_rn(v00);
                g_vt[((size_t)bi * PD_ + col + 1) * LK_ + j]     = __float2half_rn(v01);
                g_vt[((size_t)bi * PD_ + col) * LK_ + j + 8]     = __float2half_rn(v10);
                g_vt[((size_t)bi * PD_ + col + 1) * LK_ + j + 8] = __float2half_rn(v11);
            }
        }
    }
}

// ---------------------------------------------------------------------------
// Flash attention (fp16 m16n8k16), split-KV x4, post-softmax triu(k=1) mask.
// (R13 version, verbatim: K single-buffered, V double-buffered, 4 CTAs/SM.)
// ---------------------------------------------------------------------------
#define BQ  64
#define BKT 32
#define NT  (LK_ / BKT / NSPLIT)   // 16 tiles per split
#define QWP 68
#define KWP 68
#define VWP 20
#define PWP 20
#define SQ_ 0
#define SK_ (64 * QWP)                 // 4352
#define SV_ (SK_ + 32 * KWP)           // 6528  (K single buffer)
#define SP_ (SV_ + 2 * 128 * VWP)      // 11648
#define SMEM_WORDS (SP_ + 64 * PWP)    // 12928
#define SMEM_BYTES (SMEM_WORDS * 4)    // 51,712

__global__ __launch_bounds__(128, 4) void attn_kernel(const int* __restrict__ maskp)
{
    extern __shared__ uint32_t smw[];
    uint32_t* Qw = smw + SQ_;    // [r][d-words] pitch 68
    uint32_t* Kw = smw + SK_;    // [j][d-words] pitch 68, single buffer
    uint32_t* Vw = smw + SV_;    // buf*[d][j-words] pitch 20
    uint32_t* Pw = smw + SP_;    // [r][j-words] pitch 20

    const int b = blockIdx.y;
    const int qbase = blockIdx.x * BQ;
    const int split = blockIdx.z;
    const int kstart = split * (LK_ / NSPLIT);

    const __half* Qg = g_qh + ((size_t)b * LQ_ + qbase) * PD_;
    const __half* Kg = g_kh + (size_t)b * LK_ * PD_;
    const __half* Vg = g_vt + (size_t)b * PD_ * LK_;   // [d][j]

    const int tid  = threadIdx.x;
    const int wid  = tid >> 5;
    const int lane = tid & 31;
    const int lr = lane >> 2, lc = lane & 3;
    const int r0w = wid * 16;
    const int msk = *maskp;
    const float SCALE = 0.0883883476483184f;  // 1/sqrt(128)

    // Prologue: Q (8/thr), K tile 0 (4/thr), V tile 0 (4/thr) — one group
    #pragma unroll
    for (int i = 0; i < 8; i++) {
        const int g = tid + i * 128;
        const int r = g >> 4, cq = g & 15;
        __pipeline_memcpy_async(&Qw[r * QWP + cq * 4],
                                Qg + (size_t)r * PD_ + cq * 8, 16);
    }
    #pragma unroll
    for (int i = 0; i < 4; i++) {
        const int g = tid + i * 128;
        const int r = g >> 4, cq = g & 15;
        __pipeline_memcpy_async(&Kw[r * KWP + cq * 4],
                                Kg + (size_t)(kstart + r) * PD_ + cq * 8, 16);
    }
    #pragma unroll
    for (int i = 0; i < 4; i++) {
        const int g = tid + i * 128;
        const int d = g >> 2, cq = g & 3;
        __pipeline_memcpy_async(&Vw[d * VWP + cq * 4],
                                Vg + (size_t)d * LK_ + kstart + cq * 8, 16);
    }
    __pipeline_commit();

    float oacc[16][4];
    #pragma unroll
    for (int nf = 0; nf < 16; nf++)
        #pragma unroll
        for (int r = 0; r < 4; r++) oacc[nf][r] = 0.0f;
    float m_run[2] = {-1e30f, -1e30f};
    float l_run[2] = {0.0f, 0.0f};

    for (int t = 0; t < NT; t++) {
        const int kbase = kstart + t * BKT;
        const uint32_t* Vb = Vw + (t & 1) * 128 * VWP;

        __pipeline_wait_prior(0);   // K(t) and V(t) landed
        __syncthreads();            // all warps past prior-tile reads

        // Prefetch V(t+1) into the other V buffer now.
        if (t + 1 < NT) {
            uint32_t* Vn = Vw + ((t + 1) & 1) * 128 * VWP;
            #pragma unroll
            for (int i = 0; i < 4; i++) {
                const int g = tid + i * 128;
                const int d = g >> 2, cq = g & 3;
                __pipeline_memcpy_async(&Vn[d * VWP + cq * 4],
                                        Vg + (size_t)d * LK_ + kbase + BKT + cq * 8, 16);
            }
            __pipeline_commit();
        }

        // ---- S = Q @ K^T (warp: 16 rows x 32 cols; 8 kf x 4 nf = 32 MMA) ----
        float sacc[4][4];
        #pragma unroll
        for (int nf = 0; nf < 4; nf++)
            #pragma unroll
            for (int r = 0; r < 4; r++) sacc[nf][r] = 0.0f;

        #pragma unroll 4
        for (int kf = 0; kf < 8; kf++) {
            const int kw = kf * 8;
            uint32_t a[4];
            a[0] = Qw[(r0w + lr) * QWP + kw + lc];
            a[1] = Qw[(r0w + lr + 8) * QWP + kw + lc];
            a[2] = Qw[(r0w + lr) * QWP + kw + lc + 4];
            a[3] = Qw[(r0w + lr + 8) * QWP + kw + lc + 4];
            #pragma unroll
            for (int nf = 0; nf < 4; nf++) {
                uint32_t bfr[2];
                bfr[0] = Kw[(nf * 8 + lr) * KWP + kw + lc];
                bfr[1] = Kw[(nf * 8 + lr) * KWP + kw + lc + 4];
                mma_f16(sacc[nf], a, bfr);
            }
        }

        __syncthreads();            // all warps done reading Kw
        // Prefetch K(t+1) into the single K buffer; lands by next wait_prior.
        if (t + 1 < NT) {
            #pragma unroll
            for (int i = 0; i < 4; i++) {
                const int g = tid + i * 128;
                const int r = g >> 4, cq = g & 15;
                __pipeline_memcpy_async(&Kw[r * KWP + cq * 4],
                                        Kg + (size_t)(kbase + BKT + r) * PD_ + cq * 8, 16);
            }
            __pipeline_commit();
        }

        // ---- online softmax (warp-local; rows lr, lr+8) ----
        #pragma unroll
        for (int nf = 0; nf < 4; nf++)
            #pragma unroll
            for (int r = 0; r < 4; r++) sacc[nf][r] *= SCALE;

        float m_t[2] = {-1e30f, -1e30f};
        #pragma unroll
        for (int nf = 0; nf < 4; nf++) {
            m_t[0] = fmaxf(m_t[0], fmaxf(sacc[nf][0], sacc[nf][1]));
            m_t[1] = fmaxf(m_t[1], fmaxf(sacc[nf][2], sacc[nf][3]));
        }
        #pragma unroll
        for (int off = 2; off >= 1; off >>= 1) {
            m_t[0] = fmaxf(m_t[0], __shfl_xor_sync(0xffffffffu, m_t[0], off));
            m_t[1] = fmaxf(m_t[1], __shfl_xor_sync(0xffffffffu, m_t[1], off));
        }
        float m_new[2], corr[2], lp[2] = {0.0f, 0.0f};
        #pragma unroll
        for (int r = 0; r < 2; r++) {
            m_new[r] = fmaxf(m_run[r], m_t[r]);
            corr[r] = __expf(m_run[r] - m_new[r]);
        }
        #pragma unroll
        for (int nf = 0; nf < 4; nf++) {
            #pragma unroll
            for (int r = 0; r < 4; r++) {
                const float e = __expf(sacc[nf][r] - m_new[r >> 1]);
                sacc[nf][r] = e;
                lp[r >> 1] += e;
            }
        }
        #pragma unroll
        for (int off = 2; off >= 1; off >>= 1) {
            lp[0] += __shfl_xor_sync(0xffffffffu, lp[0], off);
            lp[1] += __shfl_xor_sync(0xffffffffu, lp[1], off);
        }
        #pragma unroll
        for (int r = 0; r < 2; r++) {
            l_run[r] = l_run[r] * corr[r] + lp[r];
            m_run[r] = m_new[r];
        }
        #pragma unroll
        for (int nf = 0; nf < 16; nf++) {
            oacc[nf][0] *= corr[0]; oacc[nf][1] *= corr[0];
            oacc[nf][2] *= corr[1]; oacc[nf][3] *= corr[1];
        }

        // Tile fully below/at diagonal for all rows of this CTA -> P == 0
        const bool pv_skip = msk && (kbase + BKT - 1 <= qbase);
        if (!pv_skip) {
            // masked P -> smem as packed half2 (warp-private rows)
            const int rowg0 = qbase + r0w + lr;
            const int rowg1 = rowg0 + 8;
            #pragma unroll
            for (int nf = 0; nf < 4; nf++) {
                const int col = nf * 8 + 2 * lc;
                const int kidx = kbase + col;
                const bool z00 = msk && (kidx     <= rowg0);
                const bool z01 = msk && (kidx + 1 <= rowg0);
                const bool z10 = msk && (kidx     <= rowg1);
                const bool z11 = msk && (kidx + 1 <= rowg1);
                Pw[(r0w + lr) * PWP + nf * 4 + lc] =
                    h2u(__floats2half2_rn(z00 ? 0.0f : sacc[nf][0],
                                          z01 ? 0.0f : sacc[nf][1]));
                Pw[(r0w + lr + 8) * PWP + nf * 4 + lc] =
                    h2u(__floats2half2_rn(z10 ? 0.0f : sacc[nf][2],
                                          z11 ? 0.0f : sacc[nf][3]));
            }
            __syncwarp();

            // ---- O += P @ V (2 jf x 16 nf = 32 MMA) ----
            #pragma unroll
            for (int jf = 0; jf < 2; jf++) {
                const int jw = jf * 8;
                uint32_t pa[4];
                pa[0] = Pw[(r0w + lr) * PWP + jw + lc];
                pa[1] = Pw[(r0w + lr + 8) * PWP + jw + lc];
                pa[2] = Pw[(r0w + lr) * PWP + jw + lc + 4];
                pa[3] = Pw[(r0w + lr + 8) * PWP + jw + lc + 4];
                #pragma unroll
                for (int nf = 0; nf < 16; nf++) {
                    uint32_t vb[2];
                    vb[0] = Vb[(nf * 8 + lr) * VWP + jw + lc];
                    vb[1] = Vb[(nf * 8 + lr) * VWP + jw + lc + 4];
                    mma_f16(oacc[nf], pa, vb);
                }
            }
            __syncwarp();
        }
    }

    // Epilogue: unnormalized partial O + (m, l)
    float* Pog = g_po + ((size_t)(split * B_ + b) * LQ_ + qbase) * PD_;
    #pragma unroll
    for (int nf = 0; nf < 16; nf++) {
        const int row = r0w + lr;
        const int col = nf * 8 + 2 * lc;
        *(float2*)(Pog + (size_t)row * PD_ + col) =
            make_float2(oacc[nf][0], oacc[nf][1]);
        *(float2*)(Pog + (size_t)(row + 8) * PD_ + col) =
            make_float2(oacc[nf][2], oacc[nf][3]);
    }
    if (lc == 0) {
        float* mlg = g_ml + ((size_t)(split * B_ + b) * LQ_ + qbase) * 2;
        *(float2*)(mlg + (size_t)(r0w + lr) * 2)     = make_float2(m_run[0], l_run[0]);
        *(float2*)(mlg + (size_t)(r0w + lr + 8) * 2) = make_float2(m_run[1], l_run[1]);
    }
}

// ---------------------------------------------------------------------------
// Split-KV combine over NSPLIT=4 partials.  Each thread: 4 float4 of ONE row
// (ml loaded once; all 20 loads batched for high MLP).
// ---------------------------------------------------------------------------
__global__ __launch_bounds__(256) void combine_kernel(float* __restrict__ out)
{
    const int idx = blockIdx.x * 256 + threadIdx.x;   // 65,536 threads total
    const int row = idx >> 3;                          // 8 threads per row
    const int c16 = (idx & 7) * 16;                    // 16 floats per thread

    float2 ml[NSPLIT];
    #pragma unroll
    for (int s = 0; s < NSPLIT; s++)
        ml[s] = *(const float2*)(g_ml + ((size_t)s * B_ * LQ_ + row) * 2);

    float4 p[NSPLIT][4];
    #pragma unroll
    for (int s = 0; s < NSPLIT; s++) {
        const float* base = g_po + ((size_t)s * B_ * LQ_ + row) * PD_ + c16;
        #pragma unroll
        for (int j = 0; j < 4; j++)
            p[s][j] = *(const float4*)(base + j * 4);
    }

    float m = ml[0].x;
    #pragma unroll
    for (int s = 1; s < NSPLIT; s++) m = fmaxf(m, ml[s].x);

    float w[NSPLIT], denom = 0.0f;
    #pragma unroll
    for (int s = 0; s < NSPLIT; s++) {
        w[s] = __expf(ml[s].x - m);
        denom += ml[s].y * w[s];
    }
    const float inv = 1.0f / denom;

    #pragma unroll
    for (int j = 0; j < 4; j++) {
        float4 o = make_float4(0.0f, 0.0f, 0.0f, 0.0f);
        #pragma unroll
        for (int s = 0; s < NSPLIT; s++) {
            o.x += p[s][j].x * w[s]; o.y += p[s][j].y * w[s];
            o.z += p[s][j].z * w[s]; o.w += p[s][j].w * w[s];
        }
        o.x *= inv; o.y *= inv; o.z *= inv; o.w *= inv;
        *(float4*)(out + (size_t)row * PD_ + c16 + j * 4) = o;
    }
}

// ---------------------------------------------------------------------------
extern "C" void kernel_launch(void* const* d_in, const int* in_sizes, int n_in,
                              void* d_out, int out_size)
{
    const float* x  = (const float*)d_in[0];
    const float* y  = (const float*)d_in[1];
    const float* Wq = (const float*)d_in[2];
    const float* bq = (const float*)d_in[3];
    const float* Wk = (const float*)d_in[4];
    const float* bk = (const float*)d_in[5];
    const float* Wv = (const float*)d_in[6];
    const float* bv = (const float*)d_in[7];
    const int* maskp = (const int*)d_in[8];
    float* out = (float*)d_out;

    (void)in_sizes; (void)n_in; (void)out_size;

    cudaFuncSetAttribute(attn_kernel,
                         cudaFuncAttributeMaxDynamicSharedMemorySize, SMEM_BYTES);

    wcvt_kernel<<<384, 256>>>(Wq, Wk, Wv);

    dim3 pg(128, 3);
    proj_kernel<<<pg, 128>>>(x, y, bq, bk, bv);

    dim3 ag(LQ_ / BQ, B_, NSPLIT);
    attn_kernel<<<ag, 128, SMEM_BYTES>>>(maskp);

    // 64 rows x 8 threads/row per block? No: 65,536 threads / 256 = 256 blocks.
    combine_kernel<<<256, 256>>>(out);
}

// round 15
// speedup vs baseline: 1.0274x; 1.0274x over previous
#include <cuda_runtime.h>
#include <cuda_pipeline.h>
#include <cuda_fp16.h>
#include <math.h>
#include <stdint.h>

#define B_   4
#define LQ_  2048
#define LK_  2048
#define XS_  1024
#define PD_  128
#define NSPLIT 4

// Device-global scratch (no allocation allowed).
__device__ __half g_wth[3 * PD_ * XS_];     // [mat][n][k] = half(W^T)
__device__ __half g_qh[B_ * LQ_ * PD_];     // projected q (half)
__device__ __half g_kh[B_ * LK_ * PD_];     // projected k (half)
__device__ __half g_vt[B_ * PD_ * LK_];     // projected v, TRANSPOSED [b][d][j]
__device__ float  g_po[NSPLIT * B_ * LQ_ * PD_];
__device__ float  g_ml[NSPLIT * B_ * LQ_ * 2];

// D += A*B, m16n8k16 f16 inputs, f32 accum. a: 4 words (8 halves), b: 2 words.
__device__ __forceinline__ void mma_f16(float* c, const uint32_t* a, const uint32_t* b) {
    asm volatile(
        "mma.sync.aligned.m16n8k16.row.col.f32.f16.f16.f32 "
        "{%0,%1,%2,%3}, {%4,%5,%6,%7}, {%8,%9}, {%0,%1,%2,%3};\n"
        : "+f"(c[0]), "+f"(c[1]), "+f"(c[2]), "+f"(c[3])
        : "r"(a[0]), "r"(a[1]), "r"(a[2]), "r"(a[3]), "r"(b[0]), "r"(b[1]));
}

__device__ __forceinline__ uint32_t h2u(__half2 h) {
    return *reinterpret_cast<uint32_t*>(&h);
}

// ---------------------------------------------------------------------------
// wcvt_kernel: one-time W fp32 -> half, transposed to [mat][n][k].
// ---------------------------------------------------------------------------
__global__ __launch_bounds__(256) void wcvt_kernel(
    const float* __restrict__ Wq, const float* __restrict__ Wk,
    const float* __restrict__ Wv)
{
    const int i = blockIdx.x * 256 + threadIdx.x;    // 0..98303
    const int mat = i / (PD_ * XS_ / 4);
    const int r = i % (PD_ * XS_ / 4);
    const int n = r >> 8;              // 0..127
    const int k4 = (r & 255) * 4;      // 0..1020
    const float* W = (mat == 0) ? Wq : ((mat == 1) ? Wk : Wv);
    const float f0 = W[(size_t)(k4 + 0) * PD_ + n];
    const float f1 = W[(size_t)(k4 + 1) * PD_ + n];
    const float f2 = W[(size_t)(k4 + 2) * PD_ + n];
    const float f3 = W[(size_t)(k4 + 3) * PD_ + n];
    __half2* dst = (__half2*)(g_wth + ((size_t)mat * PD_ + n) * XS_ + k4);
    dst[0] = __floats2half2_rn(f0, f1);
    dst[1] = __floats2half2_rn(f2, f3);
}

// ---------------------------------------------------------------------------
// Projection GEMM (fp16 m16n8k16), fused fp32->fp16 of A:
//   C[8192,128] = A[8192,1024]@W[1024,128]+b
// CTA tile 64x128, grid (128,3). 128 thr = 4 warps (2m x 2n), warp 32x64.
// NEW vs R13: As is DOUBLE-buffered -> ONE __syncthreads per chunk (the
// top-of-loop barrier covers both A(c)-visibility and the WAR on the buffer
// being overwritten with A(c+1)).  B (half W^T) double-buffered cp.async.
// ---------------------------------------------------------------------------
#define PAW 20
#define PBW 20

__global__ __launch_bounds__(128) void proj_kernel(
    const float* __restrict__ x, const float* __restrict__ y,
    const float* __restrict__ bq, const float* __restrict__ bk,
    const float* __restrict__ bv)
{
    __shared__ uint32_t As[2 * 64 * PAW];    // [buf][m][k-words]
    __shared__ uint32_t Bs[2 * 128 * PBW];   // [buf][n][k-words]

    const int mat = blockIdx.y;
    const float* A = (mat == 0) ? x : y;
    const float* bias = (mat == 0) ? bq : ((mat == 1) ? bk : bv);
    const __half* Bw = g_wth + (size_t)mat * PD_ * XS_;
    const int row0 = blockIdx.x * 64;

    const int tid  = threadIdx.x;
    const int wid  = tid >> 5;
    const int lane = tid & 31;
    const int lr = lane >> 2, lc = lane & 3;
    const int rw = (wid & 1) * 32;
    const int cw = (wid >> 1) * 64;

    // Prologue: LDG A(0) -> regs -> STS buf0 (no sync needed before iter-0's
    // barrier); LDG A(1) -> regs; cp.async B(0).
    float4 rA[4];
    #pragma unroll
    for (int i = 0; i < 2; i++) {
        const int g = tid + i * 128;
        const int m = g >> 2, c4 = g & 3;
        rA[2 * i]     = *(const float4*)(A + (size_t)(row0 + m) * XS_ + c4 * 8);
        rA[2 * i + 1] = *(const float4*)(A + (size_t)(row0 + m) * XS_ + c4 * 8 + 4);
    }
    #pragma unroll
    for (int i = 0; i < 2; i++) {
        const int g = tid + i * 128;
        const int m = g >> 2, c4 = g & 3;
        uint4 w;
        w.x = h2u(__floats2half2_rn(rA[2*i].x,   rA[2*i].y));
        w.y = h2u(__floats2half2_rn(rA[2*i].z,   rA[2*i].w));
        w.z = h2u(__floats2half2_rn(rA[2*i+1].x, rA[2*i+1].y));
        w.w = h2u(__floats2half2_rn(rA[2*i+1].z, rA[2*i+1].w));
        *(uint4*)&As[m * PAW + c4 * 4] = w;
    }
    #pragma unroll
    for (int i = 0; i < 2; i++) {
        const int g = tid + i * 128;
        const int m = g >> 2, c4 = g & 3;
        rA[2 * i]     = *(const float4*)(A + (size_t)(row0 + m) * XS_ + 32 + c4 * 8);
        rA[2 * i + 1] = *(const float4*)(A + (size_t)(row0 + m) * XS_ + 32 + c4 * 8 + 4);
    }
    #pragma unroll
    for (int i = 0; i < 4; i++) {
        const int g = tid + i * 128;
        const int n = g >> 2, cq = g & 3;
        __pipeline_memcpy_async(&Bs[n * PBW + cq * 4],
                                Bw + (size_t)n * XS_ + cq * 8, 16);
    }
    __pipeline_commit();

    float acc[2][8][4];
    #pragma unroll
    for (int mf = 0; mf < 2; mf++)
        #pragma unroll
        for (int nf = 0; nf < 8; nf++)
            #pragma unroll
            for (int r = 0; r < 4; r++) acc[mf][nf][r] = 0.0f;

    for (int c = 0; c < 32; c++) {
        const int buf = c & 1;
        __pipeline_wait_prior(0);   // B(c) landed
        __syncthreads();            // A(c) STS visible; WAR on buf (c+1)&1 clear

        if (c < 31) {
            // STS A(c+1) from regs into the other buffer (no barrier needed:
            // next iteration's sync orders it before any read).
            uint32_t* An = As + ((c + 1) & 1) * 64 * PAW;
            #pragma unroll
            for (int i = 0; i < 2; i++) {
                const int g = tid + i * 128;
                const int m = g >> 2, c4 = g & 3;
                uint4 w;
                w.x = h2u(__floats2half2_rn(rA[2*i].x,   rA[2*i].y));
                w.y = h2u(__floats2half2_rn(rA[2*i].z,   rA[2*i].w));
                w.z = h2u(__floats2half2_rn(rA[2*i+1].x, rA[2*i+1].y));
                w.w = h2u(__floats2half2_rn(rA[2*i+1].z, rA[2*i+1].w));
                *(uint4*)&An[m * PAW + c4 * 4] = w;
            }
            if (c < 30) {
                const int kn = (c + 2) * 32;
                #pragma unroll
                for (int i = 0; i < 2; i++) {
                    const int g = tid + i * 128;
                    const int m = g >> 2, c4 = g & 3;
                    rA[2 * i]     = *(const float4*)(A + (size_t)(row0 + m) * XS_ + kn + c4 * 8);
                    rA[2 * i + 1] = *(const float4*)(A + (size_t)(row0 + m) * XS_ + kn + c4 * 8 + 4);
                }
            }
            const int kc = (c + 1) * 32;
            const int nb = (c + 1) & 1;
            #pragma unroll
            for (int i = 0; i < 4; i++) {
                const int g = tid + i * 128;
                const int n = g >> 2, cq = g & 3;
                __pipeline_memcpy_async(&Bs[nb * 128 * PBW + n * PBW + cq * 4],
                                        Bw + (size_t)n * XS_ + kc + cq * 8, 16);
            }
            __pipeline_commit();
        }

        const uint32_t* Ab = As + buf * 64 * PAW;
        const uint32_t* Bb = Bs + buf * 128 * PBW;
        #pragma unroll
        for (int kf = 0; kf < 2; kf++) {
            const int kw = kf * 8;
            uint32_t a[2][4];
            #pragma unroll
            for (int mf = 0; mf < 2; mf++) {
                const int r = rw + mf * 16 + lr;
                a[mf][0] = Ab[r * PAW + kw + lc];
                a[mf][1] = Ab[(r + 8) * PAW + kw + lc];
                a[mf][2] = Ab[r * PAW + kw + lc + 4];
                a[mf][3] = Ab[(r + 8) * PAW + kw + lc + 4];
            }
            #pragma unroll
            for (int nf = 0; nf < 8; nf++) {
                uint32_t b[2];
                const int col = cw + nf * 8 + lr;
                b[0] = Bb[col * PBW + kw + lc];
                b[1] = Bb[col * PBW + kw + lc + 4];
                mma_f16(acc[0][nf], a[0], b);
                mma_f16(acc[1][nf], a[1], b);
            }
        }
    }

    // Epilogue: +bias, round to half.  Q/K natural layout; V transposed [b][d][j].
    #pragma unroll
    for (int mf = 0; mf < 2; mf++) {
        #pragma unroll
        for (int nf = 0; nf < 8; nf++) {
            const int row = row0 + rw + mf * 16 + lr;
            const int col = cw + nf * 8 + 2 * lc;
            const float2 bb = *(const float2*)(bias + col);
            const float v00 = acc[mf][nf][0] + bb.x;
            const float v01 = acc[mf][nf][1] + bb.y;
            const float v10 = acc[mf][nf][2] + bb.x;
            const float v11 = acc[mf][nf][3] + bb.y;
            if (mat < 2) {
                __half* C = (mat == 0) ? g_qh : g_kh;
                *(__half2*)(C + (size_t)row * PD_ + col) = __floats2half2_rn(v00, v01);
                *(__half2*)(C + (size_t)(row + 8) * PD_ + col) = __floats2half2_rn(v10, v11);
            } else {
                const int bi = row >> 11, j = row & 2047;   // row+8 stays same b
                g_vt[((size_t)bi * PD_ + col) * LK_ + j]         = __float2half_rn(v00);
                g_vt[((size_t)bi * PD_ + col + 1) * LK_ + j]     = __float2half_rn(v01);
                g_vt[((size_t)bi * PD_ + col) * LK_ + j + 8]     = __float2half_rn(v10);
                g_vt[((size_t)bi * PD_ + col + 1) * LK_ + j + 8] = __float2half_rn(v11);
            }
        }
    }
}

// ---------------------------------------------------------------------------
// Flash attention (fp16 m16n8k16), split-KV x4, post-softmax triu(k=1) mask.
// (R13 version, verbatim: K single-buffered, V double-buffered, 4 CTAs/SM.)
// ---------------------------------------------------------------------------
#define BQ  64
#define BKT 32
#define NT  (LK_ / BKT / NSPLIT)   // 16 tiles per split
#define QWP 68
#define KWP 68
#define VWP 20
#define PWP 20
#define SQ_ 0
#define SK_ (64 * QWP)                 // 4352
#define SV_ (SK_ + 32 * KWP)           // 6528  (K single buffer)
#define SP_ (SV_ + 2 * 128 * VWP)      // 11648
#define SMEM_WORDS (SP_ + 64 * PWP)    // 12928
#define SMEM_BYTES (SMEM_WORDS * 4)    // 51,712

__global__ __launch_bounds__(128, 4) void attn_kernel(const int* __restrict__ maskp)
{
    extern __shared__ uint32_t smw[];
    uint32_t* Qw = smw + SQ_;    // [r][d-words] pitch 68
    uint32_t* Kw = smw + SK_;    // [j][d-words] pitch 68, single buffer
    uint32_t* Vw = smw + SV_;    // buf*[d][j-words] pitch 20
    uint32_t* Pw = smw + SP_;    // [r][j-words] pitch 20

    const int b = blockIdx.y;
    const int qbase = blockIdx.x * BQ;
    const int split = blockIdx.z;
    const int kstart = split * (LK_ / NSPLIT);

    const __half* Qg = g_qh + ((size_t)b * LQ_ + qbase) * PD_;
    const __half* Kg = g_kh + (size_t)b * LK_ * PD_;
    const __half* Vg = g_vt + (size_t)b * PD_ * LK_;   // [d][j]

    const int tid  = threadIdx.x;
    const int wid  = tid >> 5;
    const int lane = tid & 31;
    const int lr = lane >> 2, lc = lane & 3;
    const int r0w = wid * 16;
    const int msk = *maskp;
    const float SCALE = 0.0883883476483184f;  // 1/sqrt(128)

    // Prologue: Q (8/thr), K tile 0 (4/thr), V tile 0 (4/thr) — one group
    #pragma unroll
    for (int i = 0; i < 8; i++) {
        const int g = tid + i * 128;
        const int r = g >> 4, cq = g & 15;
        __pipeline_memcpy_async(&Qw[r * QWP + cq * 4],
                                Qg + (size_t)r * PD_ + cq * 8, 16);
    }
    #pragma unroll
    for (int i = 0; i < 4; i++) {
        const int g = tid + i * 128;
        const int r = g >> 4, cq = g & 15;
        __pipeline_memcpy_async(&Kw[r * KWP + cq * 4],
                                Kg + (size_t)(kstart + r) * PD_ + cq * 8, 16);
    }
    #pragma unroll
    for (int i = 0; i < 4; i++) {
        const int g = tid + i * 128;
        const int d = g >> 2, cq = g & 3;
        __pipeline_memcpy_async(&Vw[d * VWP + cq * 4],
                                Vg + (size_t)d * LK_ + kstart + cq * 8, 16);
    }
    __pipeline_commit();

    float oacc[16][4];
    #pragma unroll
    for (int nf = 0; nf < 16; nf++)
        #pragma unroll
        for (int r = 0; r < 4; r++) oacc[nf][r] = 0.0f;
    float m_run[2] = {-1e30f, -1e30f};
    float l_run[2] = {0.0f, 0.0f};

    for (int t = 0; t < NT; t++) {
        const int kbase = kstart + t * BKT;
        const uint32_t* Vb = Vw + (t & 1) * 128 * VWP;

        __pipeline_wait_prior(0);   // K(t) and V(t) landed
        __syncthreads();            // all warps past prior-tile reads

        // Prefetch V(t+1) into the other V buffer now.
        if (t + 1 < NT) {
            uint32_t* Vn = Vw + ((t + 1) & 1) * 128 * VWP;
            #pragma unroll
            for (int i = 0; i < 4; i++) {
                const int g = tid + i * 128;
                const int d = g >> 2, cq = g & 3;
                __pipeline_memcpy_async(&Vn[d * VWP + cq * 4],
                                        Vg + (size_t)d * LK_ + kbase + BKT + cq * 8, 16);
            }
            __pipeline_commit();
        }

        // ---- S = Q @ K^T (warp: 16 rows x 32 cols; 8 kf x 4 nf = 32 MMA) ----
        float sacc[4][4];
        #pragma unroll
        for (int nf = 0; nf < 4; nf++)
            #pragma unroll
            for (int r = 0; r < 4; r++) sacc[nf][r] = 0.0f;

        #pragma unroll 4
        for (int kf = 0; kf < 8; kf++) {
            const int kw = kf * 8;
            uint32_t a[4];
            a[0] = Qw[(r0w + lr) * QWP + kw + lc];
            a[1] = Qw[(r0w + lr + 8) * QWP + kw + lc];
            a[2] = Qw[(r0w + lr) * QWP + kw + lc + 4];
            a[3] = Qw[(r0w + lr + 8) * QWP + kw + lc + 4];
            #pragma unroll
            for (int nf = 0; nf < 4; nf++) {
                uint32_t bfr[2];
                bfr[0] = Kw[(nf * 8 + lr) * KWP + kw + lc];
                bfr[1] = Kw[(nf * 8 + lr) * KWP + kw + lc + 4];
                mma_f16(sacc[nf], a, bfr);
            }
        }

        __syncthreads();            // all warps done reading Kw
        // Prefetch K(t+1) into the single K buffer; lands by next wait_prior.
        if (t + 1 < NT) {
            #pragma unroll
            for (int i = 0; i < 4; i++) {
                const int g = tid + i * 128;
                const int r = g >> 4, cq = g & 15;
                __pipeline_memcpy_async(&Kw[r * KWP + cq * 4],
                                        Kg + (size_t)(kbase + BKT + r) * PD_ + cq * 8, 16);
            }
            __pipeline_commit();
        }

        // ---- online softmax (warp-local; rows lr, lr+8) ----
        #pragma unroll
        for (int nf = 0; nf < 4; nf++)
            #pragma unroll
            for (int r = 0; r < 4; r++) sacc[nf][r] *= SCALE;

        float m_t[2] = {-1e30f, -1e30f};
        #pragma unroll
        for (int nf = 0; nf < 4; nf++) {
            m_t[0] = fmaxf(m_t[0], fmaxf(sacc[nf][0], sacc[nf][1]));
            m_t[1] = fmaxf(m_t[1], fmaxf(sacc[nf][2], sacc[nf][3]));
        }
        #pragma unroll
        for (int off = 2; off >= 1; off >>= 1) {
            m_t[0] = fmaxf(m_t[0], __shfl_xor_sync(0xffffffffu, m_t[0], off));
            m_t[1] = fmaxf(m_t[1], __shfl_xor_sync(0xffffffffu, m_t[1], off));
        }
        float m_new[2], corr[2], lp[2] = {0.0f, 0.0f};
        #pragma unroll
        for (int r = 0; r < 2; r++) {
            m_new[r] = fmaxf(m_run[r], m_t[r]);
            corr[r] = __expf(m_run[r] - m_new[r]);
        }
        #pragma unroll
        for (int nf = 0; nf < 4; nf++) {
            #pragma unroll
            for (int r = 0; r < 4; r++) {
                const float e = __expf(sacc[nf][r] - m_new[r >> 1]);
                sacc[nf][r] = e;
                lp[r >> 1] += e;
            }
        }
        #pragma unroll
        for (int off = 2; off >= 1; off >>= 1) {
            lp[0] += __shfl_xor_sync(0xffffffffu, lp[0], off);
            lp[1] += __shfl_xor_sync(0xffffffffu, lp[1], off);
        }
        #pragma unroll
        for (int r = 0; r < 2; r++) {
            l_run[r] = l_run[r] * corr[r] + lp[r];
            m_run[r] = m_new[r];
        }
        #pragma unroll
        for (int nf = 0; nf < 16; nf++) {
            oacc[nf][0] *= corr[0]; oacc[nf][1] *= corr[0];
            oacc[nf][2] *= corr[1]; oacc[nf][3] *= corr[1];
        }

        // Tile fully below/at diagonal for all rows of this CTA -> P == 0
        const bool pv_skip = msk && (kbase + BKT - 1 <= qbase);
        if (!pv_skip) {
            // masked P -> smem as packed half2 (warp-private rows)
            const int rowg0 = qbase + r0w + lr;
            const int rowg1 = rowg0 + 8;
            #pragma unroll
            for (int nf = 0; nf < 4; nf++) {
                const int col = nf * 8 + 2 * lc;
                const int kidx = kbase + col;
                const bool z00 = msk && (kidx     <= rowg0);
                const bool z01 = msk && (kidx + 1 <= rowg0);
                const bool z10 = msk && (kidx     <= rowg1);
                const bool z11 = msk && (kidx + 1 <= rowg1);
                Pw[(r0w + lr) * PWP + nf * 4 + lc] =
                    h2u(__floats2half2_rn(z00 ? 0.0f : sacc[nf][0],
                                          z01 ? 0.0f : sacc[nf][1]));
                Pw[(r0w + lr + 8) * PWP + nf * 4 + lc] =
                    h2u(__floats2half2_rn(z10 ? 0.0f : sacc[nf][2],
                                          z11 ? 0.0f : sacc[nf][3]));
            }
            __syncwarp();

            // ---- O += P @ V (2 jf x 16 nf = 32 MMA) ----
            #pragma unroll
            for (int jf = 0; jf < 2; jf++) {
                const int jw = jf * 8;
                uint32_t pa[4];
                pa[0] = Pw[(r0w + lr) * PWP + jw + lc];
                pa[1] = Pw[(r0w + lr + 8) * PWP + jw + lc];
                pa[2] = Pw[(r0w + lr) * PWP + jw + lc + 4];
                pa[3] = Pw[(r0w + lr + 8) * PWP + jw + lc + 4];
                #pragma unroll
                for (int nf = 0; nf < 16; nf++) {
                    uint32_t vb[2];
                    vb[0] = Vb[(nf * 8 + lr) * VWP + jw + lc];
                    vb[1] = Vb[(nf * 8 + lr) * VWP + jw + lc + 4];
                    mma_f16(oacc[nf], pa, vb);
                }
            }
            __syncwarp();
        }
    }

    // Epilogue: unnormalized partial O + (m, l)
    float* Pog = g_po + ((size_t)(split * B_ + b) * LQ_ + qbase) * PD_;
    #pragma unroll
    for (int nf = 0; nf < 16; nf++) {
        const int row = r0w + lr;
        const int col = nf * 8 + 2 * lc;
        *(float2*)(Pog + (size_t)row * PD_ + col) =
            make_float2(oacc[nf][0], oacc[nf][1]);
        *(float2*)(Pog + (size_t)(row + 8) * PD_ + col) =
            make_float2(oacc[nf][2], oacc[nf][3]);
    }
    if (lc == 0) {
        float* mlg = g_ml + ((size_t)(split * B_ + b) * LQ_ + qbase) * 2;
        *(float2*)(mlg + (size_t)(r0w + lr) * 2)     = make_float2(m_run[0], l_run[0]);
        *(float2*)(mlg + (size_t)(r0w + lr + 8) * 2) = make_float2(m_run[1], l_run[1]);
    }
}

// ---------------------------------------------------------------------------
// Split-KV combine over NSPLIT=4 partials.  (R13 version: one float4 per
// thread, 262,144 threads — thread count IS the MLP for this latency-bound
// kernel; the R14 4x-batched variant regressed.)
// ---------------------------------------------------------------------------
__global__ __launch_bounds__(256) void combine_kernel(float* __restrict__ out)
{
    const int idx = blockIdx.x * 256 + threadIdx.x;   // one float4 of out
    const int row = idx >> 5;                          // global (b*LQ + q)
    const int c4 = (idx & 31) * 4;

    float2 ml[NSPLIT];
    #pragma unroll
    for (int s = 0; s < NSPLIT; s++)
        ml[s] = *(const float2*)(g_ml + ((size_t)s * B_ * LQ_ + row) * 2);

    float m = ml[0].x;
    #pragma unroll
    for (int s = 1; s < NSPLIT; s++) m = fmaxf(m, ml[s].x);

    float w[NSPLIT], denom = 0.0f;
    #pragma unroll
    for (int s = 0; s < NSPLIT; s++) {
        w[s] = __expf(ml[s].x - m);
        denom += ml[s].y * w[s];
    }
    const float inv = 1.0f / denom;

    float4 o = make_float4(0.0f, 0.0f, 0.0f, 0.0f);
    #pragma unroll
    for (int s = 0; s < NSPLIT; s++) {
        const float4 p = *(const float4*)(
            g_po + ((size_t)s * B_ * LQ_ + row) * PD_ + c4);
        o.x += p.x * w[s]; o.y += p.y * w[s];
        o.z += p.z * w[s]; o.w += p.w * w[s];
    }
    o.x *= inv; o.y *= inv; o.z *= inv; o.w *= inv;
    *(float4*)(out + (size_t)row * PD_ + c4) = o;
}

// ---------------------------------------------------------------------------
extern "C" void kernel_launch(void* const* d_in, const int* in_sizes, int n_in,
                              void* d_out, int out_size)
{
    const float* x  = (const float*)d_in[0];
    const float* y  = (const float*)d_in[1];
    const float* Wq = (const float*)d_in[2];
    const float* bq = (const float*)d_in[3];
    const float* Wk = (const float*)d_in[4];
    const float* bk = (const float*)d_in[5];
    const float* Wv = (const float*)d_in[6];
    const float* bv = (const float*)d_in[7];
    const int* maskp = (const int*)d_in[8];
    float* out = (float*)d_out;

    (void)in_sizes; (void)n_in; (void)out_size;

    cudaFuncSetAttribute(attn_kernel,
                         cudaFuncAttributeMaxDynamicSharedMemorySize, SMEM_BYTES);

    wcvt_kernel<<<384, 256>>>(Wq, Wk, Wv);

    dim3 pg(128, 3);
    proj_kernel<<<pg, 128>>>(x, y, bq, bk, bv);

    dim3 ag(LQ_ / BQ, B_, NSPLIT);
    attn_kernel<<<ag, 128, SMEM_BYTES>>>(maskp);

    combine_kernel<<<(B_ * LQ_ * PD_ / 4) / 256, 256>>>(out);
}

// round 16
// speedup vs baseline: 1.0504x; 1.0224x over previous
#include <cuda_runtime.h>
#include <cuda_pipeline.h>
#include <cuda_fp16.h>
#include <math.h>
#include <stdint.h>

#define B_   4
#define LQ_  2048
#define LK_  2048
#define XS_  1024
#define PD_  128
#define NSPLIT 4

// Device-global scratch (no allocation allowed).
__device__ __half g_wth[3 * PD_ * XS_];     // [mat][n][k] = half(W^T)
__device__ __half g_qh[B_ * LQ_ * PD_];     // projected q (half)
__device__ __half g_kh[B_ * LK_ * PD_];     // projected k (half)
__device__ __half g_vt[B_ * PD_ * LK_];     // projected v, TRANSPOSED [b][d][j]
__device__ float  g_po[NSPLIT * B_ * LQ_ * PD_];
__device__ float  g_ml[NSPLIT * B_ * LQ_ * 2];

// D += A*B, m16n8k16 f16 inputs, f32 accum. a: 4 words (8 halves), b: 2 words.
__device__ __forceinline__ void mma_f16(float* c, const uint32_t* a, const uint32_t* b) {
    asm volatile(
        "mma.sync.aligned.m16n8k16.row.col.f32.f16.f16.f32 "
        "{%0,%1,%2,%3}, {%4,%5,%6,%7}, {%8,%9}, {%0,%1,%2,%3};\n"
        : "+f"(c[0]), "+f"(c[1]), "+f"(c[2]), "+f"(c[3])
        : "r"(a[0]), "r"(a[1]), "r"(a[2]), "r"(a[3]), "r"(b[0]), "r"(b[1]));
}

__device__ __forceinline__ uint32_t h2u(__half2 h) {
    return *reinterpret_cast<uint32_t*>(&h);
}

// ---------------------------------------------------------------------------
// wcvt_kernel: one-time W fp32 -> half, transposed to [mat][n][k].
// ---------------------------------------------------------------------------
__global__ __launch_bounds__(256) void wcvt_kernel(
    const float* __restrict__ Wq, const float* __restrict__ Wk,
    const float* __restrict__ Wv)
{
    const int i = blockIdx.x * 256 + threadIdx.x;    // 0..98303
    const int mat = i / (PD_ * XS_ / 4);
    const int r = i % (PD_ * XS_ / 4);
    const int n = r >> 8;              // 0..127
    const int k4 = (r & 255) * 4;      // 0..1020
    const float* W = (mat == 0) ? Wq : ((mat == 1) ? Wk : Wv);
    const float f0 = W[(size_t)(k4 + 0) * PD_ + n];
    const float f1 = W[(size_t)(k4 + 1) * PD_ + n];
    const float f2 = W[(size_t)(k4 + 2) * PD_ + n];
    const float f3 = W[(size_t)(k4 + 3) * PD_ + n];
    __half2* dst = (__half2*)(g_wth + ((size_t)mat * PD_ + n) * XS_ + k4);
    dst[0] = __floats2half2_rn(f0, f1);
    dst[1] = __floats2half2_rn(f2, f3);
}

// ---------------------------------------------------------------------------
// Projection GEMM (fp16 m16n8k16), fused fp32->fp16 of A (R13 version):
//   C[8192,128] = A[8192,1024]@W[1024,128]+b
// CTA tile 64x128, grid (128,3). 128 thr = 4 warps (2m x 2n), warp 32x64.
// Single-buffered fused-cvt A (two-sync bracket), double-buffered cp.async B.
// ---------------------------------------------------------------------------
#define PAW 20
#define PBW 20

__global__ __launch_bounds__(128) void proj_kernel(
    const float* __restrict__ x, const float* __restrict__ y,
    const float* __restrict__ bq, const float* __restrict__ bk,
    const float* __restrict__ bv)
{
    __shared__ uint32_t As[64 * PAW];        // [m][k-words], single buffer
    __shared__ uint32_t Bs[2 * 128 * PBW];   // [buf][n][k-words]

    const int mat = blockIdx.y;
    const float* A = (mat == 0) ? x : y;
    const float* bias = (mat == 0) ? bq : ((mat == 1) ? bk : bv);
    const __half* Bw = g_wth + (size_t)mat * PD_ * XS_;
    const int row0 = blockIdx.x * 64;

    const int tid  = threadIdx.x;
    const int wid  = tid >> 5;
    const int lane = tid & 31;
    const int lr = lane >> 2, lc = lane & 3;
    const int rw = (wid & 1) * 32;
    const int cw = (wid >> 1) * 64;

    // prologue: stage A(0) to regs, launch B(0)
    float4 rA[4];
    #pragma unroll
    for (int i = 0; i < 2; i++) {
        const int g = tid + i * 128;
        const int m = g >> 2, c4 = g & 3;
        rA[2 * i]     = *(const float4*)(A + (size_t)(row0 + m) * XS_ + c4 * 8);
        rA[2 * i + 1] = *(const float4*)(A + (size_t)(row0 + m) * XS_ + c4 * 8 + 4);
    }
    #pragma unroll
    for (int i = 0; i < 4; i++) {
        const int g = tid + i * 128;
        const int n = g >> 2, cq = g & 3;
        __pipeline_memcpy_async(&Bs[n * PBW + cq * 4],
                                Bw + (size_t)n * XS_ + cq * 8, 16);
    }
    __pipeline_commit();

    float acc[2][8][4];
    #pragma unroll
    for (int mf = 0; mf < 2; mf++)
        #pragma unroll
        for (int nf = 0; nf < 8; nf++)
            #pragma unroll
            for (int r = 0; r < 4; r++) acc[mf][nf][r] = 0.0f;

    for (int c = 0; c < 32; c++) {
        const int buf = c & 1;
        __pipeline_wait_prior(0);   // B(c) landed
        __syncthreads();            // all warps done reading As(c-1)

        // Store A(c): pack fp32 regs -> half2 words -> one STS.128 per slot
        #pragma unroll
        for (int i = 0; i < 2; i++) {
            const int g = tid + i * 128;
            const int m = g >> 2, c4 = g & 3;
            uint4 w;
            w.x = h2u(__floats2half2_rn(rA[2*i].x,   rA[2*i].y));
            w.y = h2u(__floats2half2_rn(rA[2*i].z,   rA[2*i].w));
            w.z = h2u(__floats2half2_rn(rA[2*i+1].x, rA[2*i+1].y));
            w.w = h2u(__floats2half2_rn(rA[2*i+1].z, rA[2*i+1].w));
            *(uint4*)&As[m * PAW + c4 * 4] = w;
        }
        __syncthreads();            // As(c) visible

        if (c < 31) {
            const int kc = (c + 1) * 32;
            #pragma unroll
            for (int i = 0; i < 2; i++) {
                const int g = tid + i * 128;
                const int m = g >> 2, c4 = g & 3;
                rA[2 * i]     = *(const float4*)(A + (size_t)(row0 + m) * XS_ + kc + c4 * 8);
                rA[2 * i + 1] = *(const float4*)(A + (size_t)(row0 + m) * XS_ + kc + c4 * 8 + 4);
            }
            const int nb = (c + 1) & 1;
            #pragma unroll
            for (int i = 0; i < 4; i++) {
                const int g = tid + i * 128;
                const int n = g >> 2, cq = g & 3;
                __pipeline_memcpy_async(&Bs[nb * 128 * PBW + n * PBW + cq * 4],
                                        Bw + (size_t)n * XS_ + kc + cq * 8, 16);
            }
            __pipeline_commit();
        }

        const uint32_t* Bb = Bs + buf * 128 * PBW;
        #pragma unroll
        for (int kf = 0; kf < 2; kf++) {
            const int kw = kf * 8;
            uint32_t a[2][4];
            #pragma unroll
            for (int mf = 0; mf < 2; mf++) {
                const int r = rw + mf * 16 + lr;
                a[mf][0] = As[r * PAW + kw + lc];
                a[mf][1] = As[(r + 8) * PAW + kw + lc];
                a[mf][2] = As[r * PAW + kw + lc + 4];
                a[mf][3] = As[(r + 8) * PAW + kw + lc + 4];
            }
            #pragma unroll
            for (int nf = 0; nf < 8; nf++) {
                uint32_t b[2];
                const int col = cw + nf * 8 + lr;
                b[0] = Bb[col * PBW + kw + lc];
                b[1] = Bb[col * PBW + kw + lc + 4];
                mma_f16(acc[0][nf], a[0], b);
                mma_f16(acc[1][nf], a[1], b);
            }
        }
    }

    // Epilogue: +bias, round to half.  Q/K natural layout; V transposed [b][d][j].
    #pragma unroll
    for (int mf = 0; mf < 2; mf++) {
        #pragma unroll
        for (int nf = 0; nf < 8; nf++) {
            const int row = row0 + rw + mf * 16 + lr;
            const int col = cw + nf * 8 + 2 * lc;
            const float2 bb = *(const float2*)(bias + col);
            const float v00 = acc[mf][nf][0] + bb.x;
            const float v01 = acc[mf][nf][1] + bb.y;
            const float v10 = acc[mf][nf][2] + bb.x;
            const float v11 = acc[mf][nf][3] + bb.y;
            if (mat < 2) {
                __half* C = (mat == 0) ? g_qh : g_kh;
                *(__half2*)(C + (size_t)row * PD_ + col) = __floats2half2_rn(v00, v01);
                *(__half2*)(C + (size_t)(row + 8) * PD_ + col) = __floats2half2_rn(v10, v11);
            } else {
                const int bi = row >> 11, j = row & 2047;   // row+8 stays same b
                g_vt[((size_t)bi * PD_ + col) * LK_ + j]         = __float2half_rn(v00);
                g_vt[((size_t)bi * PD_ + col + 1) * LK_ + j]     = __float2half_rn(v01);
                g_vt[((size_t)bi * PD_ + col) * LK_ + j + 8]     = __float2half_rn(v10);
                g_vt[((size_t)bi * PD_ + col + 1) * LK_ + j + 8] = __float2half_rn(v11);
            }
        }
    }
}

// ---------------------------------------------------------------------------
// Flash attention (fp16 m16n8k16), split-KV x4, post-softmax triu(k=1) mask.
// NEW vs R13: P never touches smem.  The S C-fragment layout maps exactly to
// the PV A-fragment layout (FA2 trick): for PV k-chunk jf, pa[0..3] =
// pack(sacc[2jf][0,1]), pack(sacc[2jf][2,3]), pack(sacc[2jf+1][0,1]),
// pack(sacc[2jf+1][2,3]).  Mask applied in-register before packing.
// Removes 8 STS + 16 LDS + 2 syncwarp per thread per active tile; smem
// drops to 46,592 B (occ 4 unchanged).  Identical rounding -> identical output.
// ---------------------------------------------------------------------------
#define BQ  64
#define BKT 32
#define NT  (LK_ / BKT / NSPLIT)   // 16 tiles per split
#define QWP 68
#define KWP 68
#define VWP 20
#define SQ_ 0
#define SK_ (64 * QWP)                 // 4352
#define SV_ (SK_ + 32 * KWP)           // 6528  (K single buffer)
#define SMEM_WORDS (SV_ + 2 * 128 * VWP)   // 11648
#define SMEM_BYTES (SMEM_WORDS * 4)        // 46,592

__global__ __launch_bounds__(128, 4) void attn_kernel(const int* __restrict__ maskp)
{
    extern __shared__ uint32_t smw[];
    uint32_t* Qw = smw + SQ_;    // [r][d-words] pitch 68
    uint32_t* Kw = smw + SK_;    // [j][d-words] pitch 68, single buffer
    uint32_t* Vw = smw + SV_;    // buf*[d][j-words] pitch 20

    const int b = blockIdx.y;
    const int qbase = blockIdx.x * BQ;
    const int split = blockIdx.z;
    const int kstart = split * (LK_ / NSPLIT);

    const __half* Qg = g_qh + ((size_t)b * LQ_ + qbase) * PD_;
    const __half* Kg = g_kh + (size_t)b * LK_ * PD_;
    const __half* Vg = g_vt + (size_t)b * PD_ * LK_;   // [d][j]

    const int tid  = threadIdx.x;
    const int wid  = tid >> 5;
    const int lane = tid & 31;
    const int lr = lane >> 2, lc = lane & 3;
    const int r0w = wid * 16;
    const int msk = *maskp;
    const float SCALE = 0.0883883476483184f;  // 1/sqrt(128)

    // Prologue: Q (8/thr), K tile 0 (4/thr), V tile 0 (4/thr) — one group
    #pragma unroll
    for (int i = 0; i < 8; i++) {
        const int g = tid + i * 128;
        const int r = g >> 4, cq = g & 15;
        __pipeline_memcpy_async(&Qw[r * QWP + cq * 4],
                                Qg + (size_t)r * PD_ + cq * 8, 16);
    }
    #pragma unroll
    for (int i = 0; i < 4; i++) {
        const int g = tid + i * 128;
        const int r = g >> 4, cq = g & 15;
        __pipeline_memcpy_async(&Kw[r * KWP + cq * 4],
                                Kg + (size_t)(kstart + r) * PD_ + cq * 8, 16);
    }
    #pragma unroll
    for (int i = 0; i < 4; i++) {
        const int g = tid + i * 128;
        const int d = g >> 2, cq = g & 3;
        __pipeline_memcpy_async(&Vw[d * VWP + cq * 4],
                                Vg + (size_t)d * LK_ + kstart + cq * 8, 16);
    }
    __pipeline_commit();

    float oacc[16][4];
    #pragma unroll
    for (int nf = 0; nf < 16; nf++)
        #pragma unroll
        for (int r = 0; r < 4; r++) oacc[nf][r] = 0.0f;
    float m_run[2] = {-1e30f, -1e30f};
    float l_run[2] = {0.0f, 0.0f};

    for (int t = 0; t < NT; t++) {
        const int kbase = kstart + t * BKT;
        const uint32_t* Vb = Vw + (t & 1) * 128 * VWP;

        __pipeline_wait_prior(0);   // K(t) and V(t) landed
        __syncthreads();            // all warps past prior-tile reads

        // Prefetch V(t+1) into the other V buffer now.
        if (t + 1 < NT) {
            uint32_t* Vn = Vw + ((t + 1) & 1) * 128 * VWP;
            #pragma unroll
            for (int i = 0; i < 4; i++) {
                const int g = tid + i * 128;
                const int d = g >> 2, cq = g & 3;
                __pipeline_memcpy_async(&Vn[d * VWP + cq * 4],
                                        Vg + (size_t)d * LK_ + kbase + BKT + cq * 8, 16);
            }
            __pipeline_commit();
        }

        // ---- S = Q @ K^T (warp: 16 rows x 32 cols; 8 kf x 4 nf = 32 MMA) ----
        float sacc[4][4];
        #pragma unroll
        for (int nf = 0; nf < 4; nf++)
            #pragma unroll
            for (int r = 0; r < 4; r++) sacc[nf][r] = 0.0f;

        #pragma unroll 4
        for (int kf = 0; kf < 8; kf++) {
            const int kw = kf * 8;
            uint32_t a[4];
            a[0] = Qw[(r0w + lr) * QWP + kw + lc];
            a[1] = Qw[(r0w + lr + 8) * QWP + kw + lc];
            a[2] = Qw[(r0w + lr) * QWP + kw + lc + 4];
            a[3] = Qw[(r0w + lr + 8) * QWP + kw + lc + 4];
            #pragma unroll
            for (int nf = 0; nf < 4; nf++) {
                uint32_t bfr[2];
                bfr[0] = Kw[(nf * 8 + lr) * KWP + kw + lc];
                bfr[1] = Kw[(nf * 8 + lr) * KWP + kw + lc + 4];
                mma_f16(sacc[nf], a, bfr);
            }
        }

        __syncthreads();            // all warps done reading Kw
        // Prefetch K(t+1) into the single K buffer; lands by next wait_prior.
        if (t + 1 < NT) {
            #pragma unroll
            for (int i = 0; i < 4; i++) {
                const int g = tid + i * 128;
                const int r = g >> 4, cq = g & 15;
                __pipeline_memcpy_async(&Kw[r * KWP + cq * 4],
                                        Kg + (size_t)(kbase + BKT + r) * PD_ + cq * 8, 16);
            }
            __pipeline_commit();
        }

        // ---- online softmax (warp-local; rows lr, lr+8) ----
        #pragma unroll
        for (int nf = 0; nf < 4; nf++)
            #pragma unroll
            for (int r = 0; r < 4; r++) sacc[nf][r] *= SCALE;

        float m_t[2] = {-1e30f, -1e30f};
        #pragma unroll
        for (int nf = 0; nf < 4; nf++) {
            m_t[0] = fmaxf(m_t[0], fmaxf(sacc[nf][0], sacc[nf][1]));
            m_t[1] = fmaxf(m_t[1], fmaxf(sacc[nf][2], sacc[nf][3]));
        }
        #pragma unroll
        for (int off = 2; off >= 1; off >>= 1) {
            m_t[0] = fmaxf(m_t[0], __shfl_xor_sync(0xffffffffu, m_t[0], off));
            m_t[1] = fmaxf(m_t[1], __shfl_xor_sync(0xffffffffu, m_t[1], off));
        }
        float m_new[2], corr[2], lp[2] = {0.0f, 0.0f};
        #pragma unroll
        for (int r = 0; r < 2; r++) {
            m_new[r] = fmaxf(m_run[r], m_t[r]);
            corr[r] = __expf(m_run[r] - m_new[r]);
        }
        #pragma unroll
        for (int nf = 0; nf < 4; nf++) {
            #pragma unroll
            for (int r = 0; r < 4; r++) {
                const float e = __expf(sacc[nf][r] - m_new[r >> 1]);
                sacc[nf][r] = e;
                lp[r >> 1] += e;
            }
        }
        #pragma unroll
        for (int off = 2; off >= 1; off >>= 1) {
            lp[0] += __shfl_xor_sync(0xffffffffu, lp[0], off);
            lp[1] += __shfl_xor_sync(0xffffffffu, lp[1], off);
        }
        #pragma unroll
        for (int r = 0; r < 2; r++) {
            l_run[r] = l_run[r] * corr[r] + lp[r];
            m_run[r] = m_new[r];
        }
        #pragma unroll
        for (int nf = 0; nf < 16; nf++) {
            oacc[nf][0] *= corr[0]; oacc[nf][1] *= corr[0];
            oacc[nf][2] *= corr[1]; oacc[nf][3] *= corr[1];
        }

        // Tile fully below/at diagonal for all rows of this CTA -> P == 0
        const bool pv_skip = msk && (kbase + BKT - 1 <= qbase);
        if (!pv_skip) {
            // Apply mask in-register (after denominator accumulation).
            if (msk) {
                const int rowg0 = qbase + r0w + lr;
                const int rowg1 = rowg0 + 8;
                #pragma unroll
                for (int nf = 0; nf < 4; nf++) {
                    const int kidx = kbase + nf * 8 + 2 * lc;
                    if (kidx     <= rowg0) sacc[nf][0] = 0.0f;
                    if (kidx + 1 <= rowg0) sacc[nf][1] = 0.0f;
                    if (kidx     <= rowg1) sacc[nf][2] = 0.0f;
                    if (kidx + 1 <= rowg1) sacc[nf][3] = 0.0f;
                }
            }

            // ---- O += P @ V: P A-frags built directly from S C-frags ----
            #pragma unroll
            for (int jf = 0; jf < 2; jf++) {
                uint32_t pa[4];
                pa[0] = h2u(__floats2half2_rn(sacc[2*jf][0],     sacc[2*jf][1]));
                pa[1] = h2u(__floats2half2_rn(sacc[2*jf][2],     sacc[2*jf][3]));
                pa[2] = h2u(__floats2half2_rn(sacc[2*jf+1][0],   sacc[2*jf+1][1]));
                pa[3] = h2u(__floats2half2_rn(sacc[2*jf+1][2],   sacc[2*jf+1][3]));
                const int jw = jf * 8;
                #pragma unroll
                for (int nf = 0; nf < 16; nf++) {
                    uint32_t vb[2];
                    vb[0] = Vb[(nf * 8 + lr) * VWP + jw + lc];
                    vb[1] = Vb[(nf * 8 + lr) * VWP + jw + lc + 4];
                    mma_f16(oacc[nf], pa, vb);
                }
            }
        }
    }

    // Epilogue: unnormalized partial O + (m, l)
    float* Pog = g_po + ((size_t)(split * B_ + b) * LQ_ + qbase) * PD_;
    #pragma unroll
    for (int nf = 0; nf < 16; nf++) {
        const int row = r0w + lr;
        const int col = nf * 8 + 2 * lc;
        *(float2*)(Pog + (size_t)row * PD_ + col) =
            make_float2(oacc[nf][0], oacc[nf][1]);
        *(float2*)(Pog + (size_t)(row + 8) * PD_ + col) =
            make_float2(oacc[nf][2], oacc[nf][3]);
    }
    if (lc == 0) {
        float* mlg = g_ml + ((size_t)(split * B_ + b) * LQ_ + qbase) * 2;
        *(float2*)(mlg + (size_t)(r0w + lr) * 2)     = make_float2(m_run[0], l_run[0]);
        *(float2*)(mlg + (size_t)(r0w + lr + 8) * 2) = make_float2(m_run[1], l_run[1]);
    }
}

// ---------------------------------------------------------------------------
// Split-KV combine over NSPLIT=4 partials (R13 version: one float4 per thread;
// thread count IS the MLP for this latency-bound kernel).
// ---------------------------------------------------------------------------
__global__ __launch_bounds__(256) void combine_kernel(float* __restrict__ out)
{
    const int idx = blockIdx.x * 256 + threadIdx.x;   // one float4 of out
    const int row = idx >> 5;                          // global (b*LQ + q)
    const int c4 = (idx & 31) * 4;

    float2 ml[NSPLIT];
    #pragma unroll
    for (int s = 0; s < NSPLIT; s++)
        ml[s] = *(const float2*)(g_ml + ((size_t)s * B_ * LQ_ + row) * 2);

    float m = ml[0].x;
    #pragma unroll
    for (int s = 1; s < NSPLIT; s++) m = fmaxf(m, ml[s].x);

    float w[NSPLIT], denom = 0.0f;
    #pragma unroll
    for (int s = 0; s < NSPLIT; s++) {
        w[s] = __expf(ml[s].x - m);
        denom += ml[s].y * w[s];
    }
    const float inv = 1.0f / denom;

    float4 o = make_float4(0.0f, 0.0f, 0.0f, 0.0f);
    #pragma unroll
    for (int s = 0; s < NSPLIT; s++) {
        const float4 p = *(const float4*)(
            g_po + ((size_t)s * B_ * LQ_ + row) * PD_ + c4);
        o.x += p.x * w[s]; o.y += p.y * w[s];
        o.z += p.z * w[s]; o.w += p.w * w[s];
    }
    o.x *= inv; o.y *= inv; o.z *= inv; o.w *= inv;
    *(float4*)(out + (size_t)row * PD_ + c4) = o;
}

// ---------------------------------------------------------------------------
extern "C" void kernel_launch(void* const* d_in, const int* in_sizes, int n_in,
                              void* d_out, int out_size)
{
    const float* x  = (const float*)d_in[0];
    const float* y  = (const float*)d_in[1];
    const float* Wq = (const float*)d_in[2];
    const float* bq = (const float*)d_in[3];
    const float* Wk = (const float*)d_in[4];
    const float* bk = (const float*)d_in[5];
    const float* Wv = (const float*)d_in[6];
    const float* bv = (const float*)d_in[7];
    const int* maskp = (const int*)d_in[8];
    float* out = (float*)d_out;

    (void)in_sizes; (void)n_in; (void)out_size;

    cudaFuncSetAttribute(attn_kernel,
                         cudaFuncAttributeMaxDynamicSharedMemorySize, SMEM_BYTES);

    wcvt_kernel<<<384, 256>>>(Wq, Wk, Wv);

    dim3 pg(128, 3);
    proj_kernel<<<pg, 128>>>(x, y, bq, bk, bv);

    dim3 ag(LQ_ / BQ, B_, NSPLIT);
    attn_kernel<<<ag, 128, SMEM_BYTES>>>(maskp);

    combine_kernel<<<(B_ * LQ_ * PD_ / 4) / 256, 256>>>(out);
}

// round 17
// speedup vs baseline: 1.0511x; 1.0007x over previous
#include <cuda_runtime.h>
#include <cuda_pipeline.h>
#include <cuda_fp16.h>
#include <math.h>
#include <stdint.h>

#define B_   4
#define LQ_  2048
#define LK_  2048
#define XS_  1024
#define PD_  128
#define NSPLIT 4

// Device-global scratch (no allocation allowed).
__device__ __half g_wth[3 * PD_ * XS_];     // [mat][n][k] = half(W^T)
__device__ __half g_qh[B_ * LQ_ * PD_];     // projected q (half)
__device__ __half g_kh[B_ * LK_ * PD_];     // projected k (half)
__device__ __half g_vt[B_ * PD_ * LK_];     // projected v, TRANSPOSED [b][d][j]
__device__ float  g_po[NSPLIT * B_ * LQ_ * PD_];
__device__ float  g_ml[NSPLIT * B_ * LQ_ * 2];

// D += A*B, m16n8k16 f16 inputs, f32 accum. a: 4 words (8 halves), b: 2 words.
__device__ __forceinline__ void mma_f16(float* c, const uint32_t* a, const uint32_t* b) {
    asm volatile(
        "mma.sync.aligned.m16n8k16.row.col.f32.f16.f16.f32 "
        "{%0,%1,%2,%3}, {%4,%5,%6,%7}, {%8,%9}, {%0,%1,%2,%3};\n"
        : "+f"(c[0]), "+f"(c[1]), "+f"(c[2]), "+f"(c[3])
        : "r"(a[0]), "r"(a[1]), "r"(a[2]), "r"(a[3]), "r"(b[0]), "r"(b[1]));
}

__device__ __forceinline__ uint32_t h2u(__half2 h) {
    return *reinterpret_cast<uint32_t*>(&h);
}

// ---------------------------------------------------------------------------
// wcvt_kernel: one-time W fp32 -> half, transposed to [mat][n][k].
// ---------------------------------------------------------------------------
__global__ __launch_bounds__(256) void wcvt_kernel(
    const float* __restrict__ Wq, const float* __restrict__ Wk,
    const float* __restrict__ Wv)
{
    const int i = blockIdx.x * 256 + threadIdx.x;    // 0..98303
    const int mat = i / (PD_ * XS_ / 4);
    const int r = i % (PD_ * XS_ / 4);
    const int n = r >> 8;              // 0..127
    const int k4 = (r & 255) * 4;      // 0..1020
    const float* W = (mat == 0) ? Wq : ((mat == 1) ? Wk : Wv);
    const float f0 = W[(size_t)(k4 + 0) * PD_ + n];
    const float f1 = W[(size_t)(k4 + 1) * PD_ + n];
    const float f2 = W[(size_t)(k4 + 2) * PD_ + n];
    const float f3 = W[(size_t)(k4 + 3) * PD_ + n];
    __half2* dst = (__half2*)(g_wth + ((size_t)mat * PD_ + n) * XS_ + k4);
    dst[0] = __floats2half2_rn(f0, f1);
    dst[1] = __floats2half2_rn(f2, f3);
}

// ---------------------------------------------------------------------------
// Projection GEMM (fp16 m16n8k16), fused fp32->fp16 of A:
//   C[8192,128] = A[8192,1024]@W[1024,128]+b
// CTA tile 64x128, grid (128,3). 128 thr = 4 warps (2m x 2n), warp 32x64.
// NEW vs R16: B uses a THREE-stage cp.async ring with exactly one commit per
// loop iteration (empty groups at the tail keep the outstanding-count
// invariant), so wait_prior(1) retires exactly B(c) while B(c+1)/B(c+2) stay
// in flight -> the per-chunk B L2-latency is no longer exposed.
// A path unchanged (single-buffered fused-cvt, two-sync bracket).
// ---------------------------------------------------------------------------
#define PAW 20
#define PBW 20

__global__ __launch_bounds__(128) void proj_kernel(
    const float* __restrict__ x, const float* __restrict__ y,
    const float* __restrict__ bq, const float* __restrict__ bk,
    const float* __restrict__ bv)
{
    __shared__ uint32_t As[64 * PAW];        // [m][k-words], single buffer
    __shared__ uint32_t Bs[3 * 128 * PBW];   // [stage][n][k-words]

    const int mat = blockIdx.y;
    const float* A = (mat == 0) ? x : y;
    const float* bias = (mat == 0) ? bq : ((mat == 1) ? bk : bv);
    const __half* Bw = g_wth + (size_t)mat * PD_ * XS_;
    const int row0 = blockIdx.x * 64;

    const int tid  = threadIdx.x;
    const int wid  = tid >> 5;
    const int lane = tid & 31;
    const int lr = lane >> 2, lc = lane & 3;
    const int rw = (wid & 1) * 32;
    const int cw = (wid >> 1) * 64;

    // Prologue: stage A(0) to regs; commit B(0) and B(1) as separate groups.
    float4 rA[4];
    #pragma unroll
    for (int i = 0; i < 2; i++) {
        const int g = tid + i * 128;
        const int m = g >> 2, c4 = g & 3;
        rA[2 * i]     = *(const float4*)(A + (size_t)(row0 + m) * XS_ + c4 * 8);
        rA[2 * i + 1] = *(const float4*)(A + (size_t)(row0 + m) * XS_ + c4 * 8 + 4);
    }
    #pragma unroll
    for (int i = 0; i < 4; i++) {
        const int g = tid + i * 128;
        const int n = g >> 2, cq = g & 3;
        __pipeline_memcpy_async(&Bs[n * PBW + cq * 4],
                                Bw + (size_t)n * XS_ + cq * 8, 16);
    }
    __pipeline_commit();   // group for B(0)
    #pragma unroll
    for (int i = 0; i < 4; i++) {
        const int g = tid + i * 128;
        const int n = g >> 2, cq = g & 3;
        __pipeline_memcpy_async(&Bs[128 * PBW + n * PBW + cq * 4],
                                Bw + (size_t)n * XS_ + 32 + cq * 8, 16);
    }
    __pipeline_commit();   // group for B(1)

    float acc[2][8][4];
    #pragma unroll
    for (int mf = 0; mf < 2; mf++)
        #pragma unroll
        for (int nf = 0; nf < 8; nf++)
            #pragma unroll
            for (int r = 0; r < 4; r++) acc[mf][nf][r] = 0.0f;

    for (int c = 0; c < 32; c++) {
        // Invariant: exactly 2 unretired commit groups at loop top.
        __pipeline_wait_prior(1);   // retire oldest -> B(c) landed
        __syncthreads();            // all warps done reading As(c-1)

        // Store A(c): pack fp32 regs -> half2 words -> one STS.128 per slot
        #pragma unroll
        for (int i = 0; i < 2; i++) {
            const int g = tid + i * 128;
            const int m = g >> 2, c4 = g & 3;
            uint4 w;
            w.x = h2u(__floats2half2_rn(rA[2*i].x,   rA[2*i].y));
            w.y = h2u(__floats2half2_rn(rA[2*i].z,   rA[2*i].w));
            w.z = h2u(__floats2half2_rn(rA[2*i+1].x, rA[2*i+1].y));
            w.w = h2u(__floats2half2_rn(rA[2*i+1].z, rA[2*i+1].w));
            *(uint4*)&As[m * PAW + c4 * 4] = w;
        }
        __syncthreads();            // As(c) visible

        if (c < 31) {
            const int kc = (c + 1) * 32;
            #pragma unroll
            for (int i = 0; i < 2; i++) {
                const int g = tid + i * 128;
                const int m = g >> 2, c4 = g & 3;
                rA[2 * i]     = *(const float4*)(A + (size_t)(row0 + m) * XS_ + kc + c4 * 8);
                rA[2 * i + 1] = *(const float4*)(A + (size_t)(row0 + m) * XS_ + kc + c4 * 8 + 4);
            }
        }
        // Issue B(c+2) into stage (c+2)%3 (or an empty group to keep count).
        if (c + 2 < 32) {
            const int kn = (c + 2) * 32;
            uint32_t* Bn = Bs + ((c + 2) % 3) * 128 * PBW;
            #pragma unroll
            for (int i = 0; i < 4; i++) {
                const int g = tid + i * 128;
                const int n = g >> 2, cq = g & 3;
                __pipeline_memcpy_async(&Bn[n * PBW + cq * 4],
                                        Bw + (size_t)n * XS_ + kn + cq * 8, 16);
            }
        }
        __pipeline_commit();        // exactly one commit per iteration

        const uint32_t* Bb = Bs + (c % 3) * 128 * PBW;
        #pragma unroll
        for (int kf = 0; kf < 2; kf++) {
            const int kw = kf * 8;
            uint32_t a[2][4];
            #pragma unroll
            for (int mf = 0; mf < 2; mf++) {
                const int r = rw + mf * 16 + lr;
                a[mf][0] = As[r * PAW + kw + lc];
                a[mf][1] = As[(r + 8) * PAW + kw + lc];
                a[mf][2] = As[r * PAW + kw + lc + 4];
                a[mf][3] = As[(r + 8) * PAW + kw + lc + 4];
            }
            #pragma unroll
            for (int nf = 0; nf < 8; nf++) {
                uint32_t b[2];
                const int col = cw + nf * 8 + lr;
                b[0] = Bb[col * PBW + kw + lc];
                b[1] = Bb[col * PBW + kw + lc + 4];
                mma_f16(acc[0][nf], a[0], b);
                mma_f16(acc[1][nf], a[1], b);
            }
        }
    }

    // Epilogue: +bias, round to half.  Q/K natural layout; V transposed [b][d][j].
    #pragma unroll
    for (int mf = 0; mf < 2; mf++) {
        #pragma unroll
        for (int nf = 0; nf < 8; nf++) {
            const int row = row0 + rw + mf * 16 + lr;
            const int col = cw + nf * 8 + 2 * lc;
            const float2 bb = *(const float2*)(bias + col);
            const float v00 = acc[mf][nf][0] + bb.x;
            const float v01 = acc[mf][nf][1] + bb.y;
            const float v10 = acc[mf][nf][2] + bb.x;
            const float v11 = acc[mf][nf][3] + bb.y;
            if (mat < 2) {
                __half* C = (mat == 0) ? g_qh : g_kh;
                *(__half2*)(C + (size_t)row * PD_ + col) = __floats2half2_rn(v00, v01);
                *(__half2*)(C + (size_t)(row + 8) * PD_ + col) = __floats2half2_rn(v10, v11);
            } else {
                const int bi = row >> 11, j = row & 2047;   // row+8 stays same b
                g_vt[((size_t)bi * PD_ + col) * LK_ + j]         = __float2half_rn(v00);
                g_vt[((size_t)bi * PD_ + col + 1) * LK_ + j]     = __float2half_rn(v01);
                g_vt[((size_t)bi * PD_ + col) * LK_ + j + 8]     = __float2half_rn(v10);
                g_vt[((size_t)bi * PD_ + col + 1) * LK_ + j + 8] = __float2half_rn(v11);
            }
        }
    }
}

// ---------------------------------------------------------------------------
// Flash attention (fp16 m16n8k16), split-KV x4, post-softmax triu(k=1) mask.
// (R16 version, verbatim: register-P FA2 PV, K single-buffered, V double-
// buffered, 46,592 B smem, 4 CTAs/SM.)
// ---------------------------------------------------------------------------
#define BQ  64
#define BKT 32
#define NT  (LK_ / BKT / NSPLIT)   // 16 tiles per split
#define QWP 68
#define KWP 68
#define VWP 20
#define SQ_ 0
#define SK_ (64 * QWP)                 // 4352
#define SV_ (SK_ + 32 * KWP)           // 6528  (K single buffer)
#define SMEM_WORDS (SV_ + 2 * 128 * VWP)   // 11648
#define SMEM_BYTES (SMEM_WORDS * 4)        // 46,592

__global__ __launch_bounds__(128, 4) void attn_kernel(const int* __restrict__ maskp)
{
    extern __shared__ uint32_t smw[];
    uint32_t* Qw = smw + SQ_;    // [r][d-words] pitch 68
    uint32_t* Kw = smw + SK_;    // [j][d-words] pitch 68, single buffer
    uint32_t* Vw = smw + SV_;    // buf*[d][j-words] pitch 20

    const int b = blockIdx.y;
    const int qbase = blockIdx.x * BQ;
    const int split = blockIdx.z;
    const int kstart = split * (LK_ / NSPLIT);

    const __half* Qg = g_qh + ((size_t)b * LQ_ + qbase) * PD_;
    const __half* Kg = g_kh + (size_t)b * LK_ * PD_;
    const __half* Vg = g_vt + (size_t)b * PD_ * LK_;   // [d][j]

    const int tid  = threadIdx.x;
    const int wid  = tid >> 5;
    const int lane = tid & 31;
    const int lr = lane >> 2, lc = lane & 3;
    const int r0w = wid * 16;
    const int msk = *maskp;
    const float SCALE = 0.0883883476483184f;  // 1/sqrt(128)

    // Prologue: Q (8/thr), K tile 0 (4/thr), V tile 0 (4/thr) — one group
    #pragma unroll
    for (int i = 0; i < 8; i++) {
        const int g = tid + i * 128;
        const int r = g >> 4, cq = g & 15;
        __pipeline_memcpy_async(&Qw[r * QWP + cq * 4],
                                Qg + (size_t)r * PD_ + cq * 8, 16);
    }
    #pragma unroll
    for (int i = 0; i < 4; i++) {
        const int g = tid + i * 128;
        const int r = g >> 4, cq = g & 15;
        __pipeline_memcpy_async(&Kw[r * KWP + cq * 4],
                                Kg + (size_t)(kstart + r) * PD_ + cq * 8, 16);
    }
    #pragma unroll
    for (int i = 0; i < 4; i++) {
        const int g = tid + i * 128;
        const int d = g >> 2, cq = g & 3;
        __pipeline_memcpy_async(&Vw[d * VWP + cq * 4],
                                Vg + (size_t)d * LK_ + kstart + cq * 8, 16);
    }
    __pipeline_commit();

    float oacc[16][4];
    #pragma unroll
    for (int nf = 0; nf < 16; nf++)
        #pragma unroll
        for (int r = 0; r < 4; r++) oacc[nf][r] = 0.0f;
    float m_run[2] = {-1e30f, -1e30f};
    float l_run[2] = {0.0f, 0.0f};

    for (int t = 0; t < NT; t++) {
        const int kbase = kstart + t * BKT;
        const uint32_t* Vb = Vw + (t & 1) * 128 * VWP;

        __pipeline_wait_prior(0);   // K(t) and V(t) landed
        __syncthreads();            // all warps past prior-tile reads

        // Prefetch V(t+1) into the other V buffer now.
        if (t + 1 < NT) {
            uint32_t* Vn = Vw + ((t + 1) & 1) * 128 * VWP;
            #pragma unroll
            for (int i = 0; i < 4; i++) {
                const int g = tid + i * 128;
                const int d = g >> 2, cq = g & 3;
                __pipeline_memcpy_async(&Vn[d * VWP + cq * 4],
                                        Vg + (size_t)d * LK_ + kbase + BKT + cq * 8, 16);
            }
            __pipeline_commit();
        }

        // ---- S = Q @ K^T (warp: 16 rows x 32 cols; 8 kf x 4 nf = 32 MMA) ----
        float sacc[4][4];
        #pragma unroll
        for (int nf = 0; nf < 4; nf++)
            #pragma unroll
            for (int r = 0; r < 4; r++) sacc[nf][r] = 0.0f;

        #pragma unroll 4
        for (int kf = 0; kf < 8; kf++) {
            const int kw = kf * 8;
            uint32_t a[4];
            a[0] = Qw[(r0w + lr) * QWP + kw + lc];
            a[1] = Qw[(r0w + lr + 8) * QWP + kw + lc];
            a[2] = Qw[(r0w + lr) * QWP + kw + lc + 4];
            a[3] = Qw[(r0w + lr + 8) * QWP + kw + lc + 4];
            #pragma unroll
            for (int nf = 0; nf < 4; nf++) {
                uint32_t bfr[2];
                bfr[0] = Kw[(nf * 8 + lr) * KWP + kw + lc];
                bfr[1] = Kw[(nf * 8 + lr) * KWP + kw + lc + 4];
                mma_f16(sacc[nf], a, bfr);
            }
        }

        __syncthreads();            // all warps done reading Kw
        // Prefetch K(t+1) into the single K buffer; lands by next wait_prior.
        if (t + 1 < NT) {
            #pragma unroll
            for (int i = 0; i < 4; i++) {
                const int g = tid + i * 128;
                const int r = g >> 4, cq = g & 15;
                __pipeline_memcpy_async(&Kw[r * KWP + cq * 4],
                                        Kg + (size_t)(kbase + BKT + r) * PD_ + cq * 8, 16);
            }
            __pipeline_commit();
        }

        // ---- online softmax (warp-local; rows lr, lr+8) ----
        #pragma unroll
        for (int nf = 0; nf < 4; nf++)
            #pragma unroll
            for (int r = 0; r < 4; r++) sacc[nf][r] *= SCALE;

        float m_t[2] = {-1e30f, -1e30f};
        #pragma unroll
        for (int nf = 0; nf < 4; nf++) {
            m_t[0] = fmaxf(m_t[0], fmaxf(sacc[nf][0], sacc[nf][1]));
            m_t[1] = fmaxf(m_t[1], fmaxf(sacc[nf][2], sacc[nf][3]));
        }
        #pragma unroll
        for (int off = 2; off >= 1; off >>= 1) {
            m_t[0] = fmaxf(m_t[0], __shfl_xor_sync(0xffffffffu, m_t[0], off));
            m_t[1] = fmaxf(m_t[1], __shfl_xor_sync(0xffffffffu, m_t[1], off));
        }
        float m_new[2], corr[2], lp[2] = {0.0f, 0.0f};
        #pragma unroll
        for (int r = 0; r < 2; r++) {
            m_new[r] = fmaxf(m_run[r], m_t[r]);
            corr[r] = __expf(m_run[r] - m_new[r]);
        }
        #pragma unroll
        for (int nf = 0; nf < 4; nf++) {
            #pragma unroll
            for (int r = 0; r < 4; r++) {
                const float e = __expf(sacc[nf][r] - m_new[r >> 1]);
                sacc[nf][r] = e;
                lp[r >> 1] += e;
            }
        }
        #pragma unroll
        for (int off = 2; off >= 1; off >>= 1) {
            lp[0] += __shfl_xor_sync(0xffffffffu, lp[0], off);
            lp[1] += __shfl_xor_sync(0xffffffffu, lp[1], off);
        }
        #pragma unroll
        for (int r = 0; r < 2; r++) {
            l_run[r] = l_run[r] * corr[r] + lp[r];
            m_run[r] = m_new[r];
        }
        #pragma unroll
        for (int nf = 0; nf < 16; nf++) {
            oacc[nf][0] *= corr[0]; oacc[nf][1] *= corr[0];
            oacc[nf][2] *= corr[1]; oacc[nf][3] *= corr[1];
        }

        // Tile fully below/at diagonal for all rows of this CTA -> P == 0
        const bool pv_skip = msk && (kbase + BKT - 1 <= qbase);
        if (!pv_skip) {
            // Apply mask in-register (after denominator accumulation).
            if (msk) {
                const int rowg0 = qbase + r0w + lr;
                const int rowg1 = rowg0 + 8;
                #pragma unroll
                for (int nf = 0; nf < 4; nf++) {
                    const int kidx = kbase + nf * 8 + 2 * lc;
                    if (kidx     <= rowg0) sacc[nf][0] = 0.0f;
                    if (kidx + 1 <= rowg0) sacc[nf][1] = 0.0f;
                    if (kidx     <= rowg1) sacc[nf][2] = 0.0f;
                    if (kidx + 1 <= rowg1) sacc[nf][3] = 0.0f;
                }
            }

            // ---- O += P @ V: P A-frags built directly from S C-frags ----
            #pragma unroll
            for (int jf = 0; jf < 2; jf++) {
                uint32_t pa[4];
                pa[0] = h2u(__floats2half2_rn(sacc[2*jf][0],     sacc[2*jf][1]));
                pa[1] = h2u(__floats2half2_rn(sacc[2*jf][2],     sacc[2*jf][3]));
                pa[2] = h2u(__floats2half2_rn(sacc[2*jf+1][0],   sacc[2*jf+1][1]));
                pa[3] = h2u(__floats2half2_rn(sacc[2*jf+1][2],   sacc[2*jf+1][3]));
                const int jw = jf * 8;
                #pragma unroll
                for (int nf = 0; nf < 16; nf++) {
                    uint32_t vb[2];
                    vb[0] = Vb[(nf * 8 + lr) * VWP + jw + lc];
                    vb[1] = Vb[(nf * 8 + lr) * VWP + jw + lc + 4];
                    mma_f16(oacc[nf], pa, vb);
                }
            }
        }
    }

    // Epilogue: unnormalized partial O + (m, l)
    float* Pog = g_po + ((size_t)(split * B_ + b) * LQ_ + qbase) * PD_;
    #pragma unroll
    for (int nf = 0; nf < 16; nf++) {
        const int row = r0w + lr;
        const int col = nf * 8 + 2 * lc;
        *(float2*)(Pog + (size_t)row * PD_ + col) =
            make_float2(oacc[nf][0], oacc[nf][1]);
        *(float2*)(Pog + (size_t)(row + 8) * PD_ + col) =
            make_float2(oacc[nf][2], oacc[nf][3]);
    }
    if (lc == 0) {
        float* mlg = g_ml + ((size_t)(split * B_ + b) * LQ_ + qbase) * 2;
        *(float2*)(mlg + (size_t)(r0w + lr) * 2)     = make_float2(m_run[0], l_run[0]);
        *(float2*)(mlg + (size_t)(r0w + lr + 8) * 2) = make_float2(m_run[1], l_run[1]);
    }
}

// ---------------------------------------------------------------------------
// Split-KV combine over NSPLIT=4 partials (one float4 per thread; thread
// count IS the MLP for this latency-bound kernel).
// ---------------------------------------------------------------------------
__global__ __launch_bounds__(256) void combine_kernel(float* __restrict__ out)
{
    const int idx = blockIdx.x * 256 + threadIdx.x;   // one float4 of out
    const int row = idx >> 5;                          // global (b*LQ + q)
    const int c4 = (idx & 31) * 4;

    float2 ml[NSPLIT];
    #pragma unroll
    for (int s = 0; s < NSPLIT; s++)
        ml[s] = *(const float2*)(g_ml + ((size_t)s * B_ * LQ_ + row) * 2);

    float m = ml[0].x;
    #pragma unroll
    for (int s = 1; s < NSPLIT; s++) m = fmaxf(m, ml[s].x);

    float w[NSPLIT], denom = 0.0f;
    #pragma unroll
    for (int s = 0; s < NSPLIT; s++) {
        w[s] = __expf(ml[s].x - m);
        denom += ml[s].y * w[s];
    }
    const float inv = 1.0f / denom;

    float4 o = make_float4(0.0f, 0.0f, 0.0f, 0.0f);
    #pragma unroll
    for (int s = 0; s < NSPLIT; s++) {
        const float4 p = *(const float4*)(
            g_po + ((size_t)s * B_ * LQ_ + row) * PD_ + c4);
        o.x += p.x * w[s]; o.y += p.y * w[s];
        o.z += p.z * w[s]; o.w += p.w * w[s];
    }
    o.x *= inv; o.y *= inv; o.z *= inv; o.w *= inv;
    *(float4*)(out + (size_t)row * PD_ + c4) = o;
}

// ---------------------------------------------------------------------------
extern "C" void kernel_launch(void* const* d_in, const int* in_sizes, int n_in,
                              void* d_out, int out_size)
{
    const float* x  = (const float*)d_in[0];
    const float* y  = (const float*)d_in[1];
    const float* Wq = (const float*)d_in[2];
    const float* bq = (const float*)d_in[3];
    const float* Wk = (const float*)d_in[4];
    const float* bk = (const float*)d_in[5];
    const float* Wv = (const float*)d_in[6];
    const float* bv = (const float*)d_in[7];
    const int* maskp = (const int*)d_in[8];
    float* out = (float*)d_out;

    (void)in_sizes; (void)n_in; (void)out_size;

    cudaFuncSetAttribute(attn_kernel,
                         cudaFuncAttributeMaxDynamicSharedMemorySize, SMEM_BYTES);

    wcvt_kernel<<<384, 256>>>(Wq, Wk, Wv);

    dim3 pg(128, 3);
    proj_kernel<<<pg, 128>>>(x, y, bq, bk, bv);

    dim3 ag(LQ_ / BQ, B_, NSPLIT);
    attn_kernel<<<ag, 128, SMEM_BYTES>>>(maskp);

    combine_kernel<<<(B_ * LQ_ * PD_ / 4) / 256, 256>>>(out);
}